// round 10
// baseline (speedup 1.0000x reference)
#include <cuda_runtime.h>
#include <cuda_bf16.h>
#include <math.h>

// Problem constants (fixed-shape problem)
#define NMAX 50048
#define EMAX 800000

// ---------------- device scratch (no allocations allowed) ----------------
__device__ int    g_cnt[NMAX];
__device__ int    g_rowptr[NMAX + 2];
__device__ int    g_wcur[NMAX];
__device__ int    g_eid[EMAX];
__device__ float  g_w0[EMAX];
__device__ float  g_w1[EMAX];
__device__ float  g_w2[EMAX];
__device__ float4 g_wp[EMAX];          // normalized (w0,w1,w2,0) in CSR order
__device__ float  g_ssum0[NMAX];       // after scan3: holds 1/sum (or 0)
__device__ float  g_ssum1[NMAX];
__device__ float  g_ssum2[NMAX];
__device__ float  g_agg[50000 * 384];
__device__ float  g_ctx[50000 * 128];
__device__ float  g_h[50000 * 128];
__device__ int    g_chunk[64];
__device__ int    g_chunkoff[64];

// ---------------- small helpers ----------------
__device__ __forceinline__ unsigned f2tf(float x) {
    unsigned r;
    asm("cvt.rna.tf32.f32 %0, %1;" : "=r"(r) : "f"(x));
    return r;
}
__device__ __forceinline__ unsigned s2u(const void* p) {
    unsigned r;
    asm("{ .reg .u64 t; cvta.to.shared.u64 t, %1; cvt.u32.u64 %0, t; }"
        : "=r"(r) : "l"(p));
    return r;
}
#define CP16(dst, src, sz) \
    asm volatile("cp.async.cg.shared.global [%0], [%1], 16, %2;" \
                 :: "r"(dst), "l"(src), "r"(sz))
#define CPCOMMIT() asm volatile("cp.async.commit_group;")
#define CPWAIT(n)  asm volatile("cp.async.wait_group %0;" :: "n"(n))
#define MMA_TF32(acc, a0, a1, a2, a3, b0, b1) \
    asm volatile( \
        "mma.sync.aligned.m16n8k8.row.col.f32.tf32.tf32.f32 " \
        "{%0,%1,%2,%3}, {%4,%5,%6,%7}, {%8,%9}, {%0,%1,%2,%3};" \
        : "+f"((acc)[0]), "+f"((acc)[1]), "+f"((acc)[2]), "+f"((acc)[3]) \
        : "r"(a0), "r"(a1), "r"(a2), "r"(a3), "r"(b0), "r"(b1))

// ---------------- init ----------------
__global__ void k_init(int N) {
    int i = blockIdx.x * blockDim.x + threadIdx.x;
    if (i < N) {
        g_cnt[i] = 0;
        g_ssum0[i] = 0.f; g_ssum1[i] = 0.f; g_ssum2[i] = 0.f;
    }
}

// ---------------- edge pass 1: histogram + exp + exp-sums ----------------
__global__ void k_edge1(const int* __restrict__ dst,
                        const float* __restrict__ l1,
                        const float* __restrict__ l2,
                        const float* __restrict__ l3, int E) {
    int e = blockIdx.x * blockDim.x + threadIdx.x;
    if (e >= E) return;
    int d = dst[e];
    atomicAdd(&g_cnt[d], 1);
    float w0 = __expf(l1[e]);
    float w1 = __expf(l2[e]);
    float w2 = __expf(l3[e]);
    g_w0[e] = w0; g_w1[e] = w1; g_w2[e] = w2;
    atomicAdd(&g_ssum0[d], w0);
    atomicAdd(&g_ssum1[d], w1);
    atomicAdd(&g_ssum2[d], w2);
}

// ---------------- scan (two-level) ----------------
__global__ void k_scan1(int N) {
    __shared__ int sh[1024];
    int t = threadIdx.x;
    int n = blockIdx.x * 1024 + t;
    int v = (n < N) ? g_cnt[n] : 0;
    sh[t] = v;
    __syncthreads();
#pragma unroll
    for (int off = 1; off < 1024; off <<= 1) {
        int x = (t >= off) ? sh[t - off] : 0;
        __syncthreads();
        sh[t] += x;
        __syncthreads();
    }
    if (n < N) g_rowptr[n] = sh[t] - v;
    if (t == 1023) g_chunk[blockIdx.x] = sh[1023];
}

__global__ void k_scan2(int nch) {
    __shared__ int sh[64];
    int t = threadIdx.x;
    if (t < nch) sh[t] = g_chunk[t];
    __syncthreads();
    if (t == 0) {
        int run = 0;
        for (int i = 0; i < nch; i++) { int tmp = sh[i]; sh[i] = run; run += tmp; }
    }
    __syncthreads();
    if (t < nch) g_chunkoff[t] = sh[t];
}

__global__ void k_scan3(int N, int E) {
    int n = blockIdx.x * 1024 + threadIdx.x;
    if (n < N) {
        int v = g_rowptr[n] + g_chunkoff[blockIdx.x];
        g_rowptr[n] = v;
        g_wcur[n] = v;
        float s0 = g_ssum0[n]; g_ssum0[n] = (s0 > 0.f) ? 1.f / s0 : 0.f;
        float s1 = g_ssum1[n]; g_ssum1[n] = (s1 > 0.f) ? 1.f / s1 : 0.f;
        float s2 = g_ssum2[n]; g_ssum2[n] = (s2 > 0.f) ? 1.f / s2 : 0.f;
    }
    if (n == 0) g_rowptr[N] = E;
}

// ---------------- edge pass 2: scatter edge ids + normalized packed weights ----
__global__ void k_edge2(const int* __restrict__ dst, int E) {
    int e = blockIdx.x * blockDim.x + threadIdx.x;
    if (e >= E) return;
    int d = dst[e];
    int p = atomicAdd(&g_wcur[d], 1);
    g_eid[p] = e;
    float4 w;
    w.x = g_w0[e] * g_ssum0[d];
    w.y = g_w1[e] * g_ssum1[d];
    w.z = g_w2[e] * g_ssum2[d];
    w.w = 0.f;
    g_wp[p] = w;
}

// ---------------- gather: agg_i[n] = sum_e a_i(e) * ef_i[e] ----------------
__global__ void k_gather(const float4* __restrict__ ef1,
                         const float4* __restrict__ ef2,
                         const float4* __restrict__ ef3, int N) {
    int warp = blockIdx.x * 8 + (threadIdx.x >> 5);
    int lane = threadIdx.x & 31;
    if (warp >= N) return;
    int s = g_rowptr[warp];
    int eend = g_rowptr[warp + 1];
    float4 a0 = {0, 0, 0, 0}, a1 = {0, 0, 0, 0}, a2 = {0, 0, 0, 0};
    int k = s;
    for (; k + 4 <= eend; k += 4) {
        int e0 = g_eid[k], e1 = g_eid[k + 1], e2 = g_eid[k + 2], e3 = g_eid[k + 3];
        float4 wA = g_wp[k], wB = g_wp[k + 1], wC = g_wp[k + 2], wD = g_wp[k + 3];
        float4 u0 = ef1[e0 * 32 + lane], u1 = ef1[e1 * 32 + lane];
        float4 u2 = ef1[e2 * 32 + lane], u3 = ef1[e3 * 32 + lane];
        float4 v0 = ef2[e0 * 32 + lane], v1 = ef2[e1 * 32 + lane];
        float4 v2 = ef2[e2 * 32 + lane], v3 = ef2[e3 * 32 + lane];
        float4 x0 = ef3[e0 * 32 + lane], x1 = ef3[e1 * 32 + lane];
        float4 x2 = ef3[e2 * 32 + lane], x3 = ef3[e3 * 32 + lane];
        a0.x += wA.x * u0.x + wB.x * u1.x + wC.x * u2.x + wD.x * u3.x;
        a0.y += wA.x * u0.y + wB.x * u1.y + wC.x * u2.y + wD.x * u3.y;
        a0.z += wA.x * u0.z + wB.x * u1.z + wC.x * u2.z + wD.x * u3.z;
        a0.w += wA.x * u0.w + wB.x * u1.w + wC.x * u2.w + wD.x * u3.w;
        a1.x += wA.y * v0.x + wB.y * v1.x + wC.y * v2.x + wD.y * v3.x;
        a1.y += wA.y * v0.y + wB.y * v1.y + wC.y * v2.y + wD.y * v3.y;
        a1.z += wA.y * v0.z + wB.y * v1.z + wC.y * v2.z + wD.y * v3.z;
        a1.w += wA.y * v0.w + wB.y * v1.w + wC.y * v2.w + wD.y * v3.w;
        a2.x += wA.z * x0.x + wB.z * x1.x + wC.z * x2.x + wD.z * x3.x;
        a2.y += wA.z * x0.y + wB.z * x1.y + wC.z * x2.y + wD.z * x3.y;
        a2.z += wA.z * x0.z + wB.z * x1.z + wC.z * x2.z + wD.z * x3.z;
        a2.w += wA.z * x0.w + wB.z * x1.w + wC.z * x2.w + wD.z * x3.w;
    }
    for (; k < eend; k++) {
        int e = g_eid[k];
        float4 w = g_wp[k];
        float4 u = ef1[e * 32 + lane];
        float4 v = ef2[e * 32 + lane];
        float4 x = ef3[e * 32 + lane];
        a0.x += w.x * u.x; a0.y += w.x * u.y; a0.z += w.x * u.z; a0.w += w.x * u.w;
        a1.x += w.y * v.x; a1.y += w.y * v.y; a1.z += w.y * v.z; a1.w += w.y * v.w;
        a2.x += w.z * x.x; a2.y += w.z * x.y; a2.z += w.z * x.z; a2.w += w.z * x.w;
    }
    float4* out = reinterpret_cast<float4*>(g_agg) + warp * 96;
    out[lane]      = a0;
    out[32 + lane] = a1;
    out[64 + lane] = a2;
}

// ---------------- TF32 tensor-core GEMM (cp.async 3-stage) -- used for G2b ----
struct TriC { const float* p0; const float* p1; const float* p2; };
struct TriO { float* p0; float* p1; float* p2; };
__device__ __forceinline__ const float* sel(const TriC& t, int z) {
    return z == 0 ? t.p0 : (z == 1 ? t.p1 : t.p2);
}
__device__ __forceinline__ float* sel(const TriO& t, int z) {
    return z == 0 ? t.p0 : (z == 1 ? t.p1 : t.p2);
}

#define GEMM_ASZ (128 * 36)
#define GEMM_BSZ (32 * 136)
#define GEMM_STAGE (GEMM_ASZ + GEMM_BSZ)
#define GEMM_SMEM (3 * GEMM_STAGE * 4)

template <int KTOT, int EPI, bool CONCAT3>
__global__ __launch_bounds__(256, 2)
void gemm_tc(TriC a0t, const float* __restrict__ A1, const float* __restrict__ A2,
             int lda, TriC bt, int ldb, TriC biast, TriC flagt,
             TriO ct, int ldc, int M) {
    extern __shared__ float smem[];
    const int z = blockIdx.z;
    const float* __restrict__ A0 = sel(a0t, z);
    const float* __restrict__ B = sel(bt, z);
    const float* __restrict__ bias = sel(biast, z);
    const float* __restrict__ flag_s = sel(flagt, z);
    float* __restrict__ C = sel(ct, z);

    const int t = threadIdx.x;
    const int lane = t & 31;
    const int warp = t >> 5;
    const int warpM = warp >> 1;
    const int warpN = warp & 1;
    const int row0 = blockIdx.x * 128;
    const int coff = blockIdx.y * 128;

    float acc[2][8][4];
#pragma unroll
    for (int i = 0; i < 2; i++)
#pragma unroll
        for (int j = 0; j < 8; j++)
#pragma unroll
            for (int q = 0; q < 4; q++) acc[i][j][q] = 0.f;

    const int ar = lane >> 2, ac = lane & 3;
    const int bk = lane & 3, bn = lane >> 2;
    const int NKB = KTOT / 32;

    auto issue_tile = [&](int kb) {
        float* stage = smem + (kb % 3) * GEMM_STAGE;
        float* As = stage;
        float* Bs = stage + GEMM_ASZ;
        int k0 = kb * 32;
#pragma unroll
        for (int i = 0; i < 4; i++) {
            int lin = t + i * 256;
            int r = lin >> 3;
            int kk = (lin & 7) << 2;
            int grow = row0 + r;
            bool ok = grow < M;
            const float* src;
            int kg = k0 + kk;
            if (CONCAT3) {
                const float* Ap = (kg < 128) ? A0 : ((kg < 256) ? A1 : A2);
                src = ok ? (Ap + grow * 128 + (kg & 127)) : A0;
            } else {
                src = ok ? (A0 + grow * lda + kg) : A0;
            }
            CP16(s2u(As + r * 36 + kk), src, ok ? 16 : 0);
        }
#pragma unroll
        for (int i = 0; i < 4; i++) {
            int lin = t + i * 256;
            int kr = lin >> 5;
            int nn = (lin & 31) << 2;
            CP16(s2u(Bs + kr * 136 + nn), B + (k0 + kr) * ldb + coff + nn, 16);
        }
    };

    issue_tile(0); CPCOMMIT();
    if (NKB > 1) { issue_tile(1); CPCOMMIT(); }

    for (int kb = 0; kb < NKB; kb++) {
        if (kb + 1 < NKB) { CPWAIT(1); } else { CPWAIT(0); }
        __syncthreads();
        if (kb + 2 < NKB) { issue_tile(kb + 2); CPCOMMIT(); }

        float* stage = smem + (kb % 3) * GEMM_STAGE;
        float* As = stage;
        float* Bs = stage + GEMM_ASZ;
#pragma unroll
        for (int kk = 0; kk < 32; kk += 8) {
            unsigned af[2][4];
#pragma unroll
            for (int mi = 0; mi < 2; mi++) {
                int rb = warpM * 32 + mi * 16;
                af[mi][0] = f2tf(As[(rb + ar) * 36 + kk + ac]);
                af[mi][1] = f2tf(As[(rb + ar + 8) * 36 + kk + ac]);
                af[mi][2] = f2tf(As[(rb + ar) * 36 + kk + ac + 4]);
                af[mi][3] = f2tf(As[(rb + ar + 8) * 36 + kk + ac + 4]);
            }
            unsigned bf[8][2];
#pragma unroll
            for (int ni = 0; ni < 8; ni++) {
                int nb = warpN * 64 + ni * 8;
                bf[ni][0] = f2tf(Bs[(kk + bk) * 136 + nb + bn]);
                bf[ni][1] = f2tf(Bs[(kk + bk + 4) * 136 + nb + bn]);
            }
#pragma unroll
            for (int mi = 0; mi < 2; mi++)
#pragma unroll
                for (int ni = 0; ni < 8; ni++)
                    MMA_TF32(acc[mi][ni], af[mi][0], af[mi][1], af[mi][2],
                             af[mi][3], bf[ni][0], bf[ni][1]);
        }
    }

#pragma unroll
    for (int mi = 0; mi < 2; mi++) {
        int rA = row0 + warpM * 32 + mi * 16 + (lane >> 2);
        int rB = rA + 8;
        float flA = 1.f, flB = 1.f;
        if (EPI == 1) {
            flA = (rA < M && flag_s[rA] > 0.f) ? 1.f : 0.f;
            flB = (rB < M && flag_s[rB] > 0.f) ? 1.f : 0.f;
        }
#pragma unroll
        for (int ni = 0; ni < 8; ni++) {
            int col = coff + warpN * 64 + ni * 8 + (lane & 3) * 2;
            float b0 = bias[col], b1 = bias[col + 1];
            if (rA < M) {
                float v0, v1;
                if (EPI == 1) {
                    v0 = acc[mi][ni][0] + b0 * flA;
                    v1 = acc[mi][ni][1] + b1 * flA;
                    v0 = (v0 > 0.f) ? v0 : expm1f(v0);
                    v1 = (v1 > 0.f) ? v1 : expm1f(v1);
                } else {
                    v0 = acc[mi][ni][0] + b0;
                    v1 = acc[mi][ni][1] + b1;
                }
                *reinterpret_cast<float2*>(&C[rA * ldc + col]) = make_float2(v0, v1);
            }
            if (rB < M) {
                float v2, v3;
                if (EPI == 1) {
                    v2 = acc[mi][ni][2] + b0 * flB;
                    v3 = acc[mi][ni][3] + b1 * flB;
                    v2 = (v2 > 0.f) ? v2 : expm1f(v2);
                    v3 = (v3 > 0.f) ? v3 : expm1f(v3);
                } else {
                    v2 = acc[mi][ni][2] + b0;
                    v3 = acc[mi][ni][3] + b1;
                }
                *reinterpret_cast<float2*>(&C[rB * ldc + col]) = make_float2(v2, v3);
            }
        }
    }
}

// ---------------- fused G1+G2a: ctx = elu-blocks(agg) @ Wa + ba ----------------
// per 128-row tile: for j=0..2:
//   phase1: c_j = elu(agg[:, j*128:] @ W_j + b_j*flag_j)   -> smem Cs (tf32)
//   phase2: ctx += Cs @ Wa[j*128:(j+1)*128, :]
// final: ctx += ba, write gmem. Eliminates the g_c global round-trip.
#define CTX_AS 36           // A stage stride (mod32=4, conflict-free frag reads)
#define CTX_BS 136          // B stage stride (mod32=8, conflict-free)
#define CTX_CS 133          // c-tile stride (mod32=5, conflict-free store+read)
#define CTX_SMEM ((128 * CTX_AS + 32 * CTX_BS + 128 * CTX_CS) * 4)

__global__ __launch_bounds__(256)
void k_ctx(const float* __restrict__ agg,
           TriC wt, TriC biast, TriC flagt,
           const float* __restrict__ Wa, const float* __restrict__ ba,
           float* __restrict__ ctx, int M) {
    extern __shared__ unsigned smu[];
    unsigned (*As)[CTX_AS] = (unsigned(*)[CTX_AS])smu;
    unsigned (*Bs)[CTX_BS] = (unsigned(*)[CTX_BS])(smu + 128 * CTX_AS);
    unsigned (*Cs)[CTX_CS] =
        (unsigned(*)[CTX_CS])(smu + 128 * CTX_AS + 32 * CTX_BS);

    const int t = threadIdx.x;
    const int lane = t & 31;
    const int warp = t >> 5;
    const int warpM = warp >> 1;
    const int warpN = warp & 1;
    const int row0 = blockIdx.x * 128;

    const int ar = lane >> 2, ac = lane & 3;
    const int bk = lane & 3, bn = lane >> 2;

    float accX[2][8][4];   // ctx accumulator (persists across j)
#pragma unroll
    for (int i = 0; i < 2; i++)
#pragma unroll
        for (int j = 0; j < 8; j++)
#pragma unroll
            for (int q = 0; q < 4; q++) accX[i][j][q] = 0.f;

    for (int j = 0; j < 3; j++) {
        const float* __restrict__ Wj = sel(wt, j);
        const float* __restrict__ bj = sel(biast, j);
        const float* __restrict__ fj = sel(flagt, j);

        float acc1[2][8][4];
#pragma unroll
        for (int i = 0; i < 2; i++)
#pragma unroll
            for (int n = 0; n < 8; n++)
#pragma unroll
                for (int q = 0; q < 4; q++) acc1[i][n][q] = 0.f;

        // phase 1: acc1 = agg[:, j*128 .. +128] @ W_j
        for (int k0 = 0; k0 < 128; k0 += 32) {
            __syncthreads();   // protect As/Bs (read in previous step / phase2)
#pragma unroll
            for (int i = 0; i < 4; i++) {
                int lin = t + i * 256;
                int r = lin >> 3;
                int kk = (lin & 7) << 2;
                int grow = row0 + r;
                float4 v = {0, 0, 0, 0};
                if (grow < M)
                    v = *reinterpret_cast<const float4*>(
                        agg + (size_t)grow * 384 + j * 128 + k0 + kk);
                As[r][kk + 0] = f2tf(v.x); As[r][kk + 1] = f2tf(v.y);
                As[r][kk + 2] = f2tf(v.z); As[r][kk + 3] = f2tf(v.w);
            }
#pragma unroll
            for (int i = 0; i < 2; i++) {
                int lin = t + i * 256;
                int kr = lin >> 4;            // 0..31
                int nn = (lin & 15) << 3;     // 0..120 step 8
                float4 v0 = *reinterpret_cast<const float4*>(
                    Wj + (k0 + kr) * 128 + nn);
                float4 v1 = *reinterpret_cast<const float4*>(
                    Wj + (k0 + kr) * 128 + nn + 4);
                Bs[kr][nn + 0] = f2tf(v0.x); Bs[kr][nn + 1] = f2tf(v0.y);
                Bs[kr][nn + 2] = f2tf(v0.z); Bs[kr][nn + 3] = f2tf(v0.w);
                Bs[kr][nn + 4] = f2tf(v1.x); Bs[kr][nn + 5] = f2tf(v1.y);
                Bs[kr][nn + 6] = f2tf(v1.z); Bs[kr][nn + 7] = f2tf(v1.w);
            }
            __syncthreads();
#pragma unroll
            for (int kk = 0; kk < 32; kk += 8) {
                unsigned af[2][4];
#pragma unroll
                for (int mi = 0; mi < 2; mi++) {
                    int rb = warpM * 32 + mi * 16;
                    af[mi][0] = As[rb + ar][kk + ac];
                    af[mi][1] = As[rb + ar + 8][kk + ac];
                    af[mi][2] = As[rb + ar][kk + ac + 4];
                    af[mi][3] = As[rb + ar + 8][kk + ac + 4];
                }
#pragma unroll
                for (int ni = 0; ni < 8; ni++) {
                    int nb = warpN * 64 + ni * 8;
                    unsigned b0 = Bs[kk + bk][nb + bn];
                    unsigned b1 = Bs[kk + bk + 4][nb + bn];
#pragma unroll
                    for (int mi = 0; mi < 2; mi++)
                        MMA_TF32(acc1[mi][ni], af[mi][0], af[mi][1], af[mi][2],
                                 af[mi][3], b0, b1);
                }
            }
        }

        // epilogue 1: elu(acc1 + b_j*flag) -> Cs (tf32)
        // (all threads have passed the phase-1 syncs, so prior phase-2 Cs
        //  reads are complete)
#pragma unroll
        for (int mi = 0; mi < 2; mi++) {
            int rloc = warpM * 32 + mi * 16 + (lane >> 2);
            int rA = row0 + rloc;
            int rB = rA + 8;
            float flA = (rA < M && fj[rA] > 0.f) ? 1.f : 0.f;
            float flB = (rB < M && fj[rB] > 0.f) ? 1.f : 0.f;
#pragma unroll
            for (int ni = 0; ni < 8; ni++) {
                int col = warpN * 64 + ni * 8 + (lane & 3) * 2;
                float b0 = bj[col], b1 = bj[col + 1];
                float v0 = acc1[mi][ni][0] + b0 * flA;
                float v1 = acc1[mi][ni][1] + b1 * flA;
                float v2 = acc1[mi][ni][2] + b0 * flB;
                float v3 = acc1[mi][ni][3] + b1 * flB;
                v0 = (v0 > 0.f) ? v0 : expm1f(v0);
                v1 = (v1 > 0.f) ? v1 : expm1f(v1);
                v2 = (v2 > 0.f) ? v2 : expm1f(v2);
                v3 = (v3 > 0.f) ? v3 : expm1f(v3);
                Cs[rloc][col]     = f2tf(v0);
                Cs[rloc][col + 1] = f2tf(v1);
                Cs[rloc + 8][col]     = f2tf(v2);
                Cs[rloc + 8][col + 1] = f2tf(v3);
            }
        }
        __syncthreads();

        // phase 2: accX += Cs @ Wa[j*128 .. , 0:128]
        for (int k0 = 0; k0 < 128; k0 += 32) {
            if (k0 > 0) __syncthreads();   // protect Bs reads of previous step
#pragma unroll
            for (int i = 0; i < 2; i++) {
                int lin = t + i * 256;
                int kr = lin >> 4;
                int nn = (lin & 15) << 3;
                float4 v0 = *reinterpret_cast<const float4*>(
                    Wa + (size_t)(j * 128 + k0 + kr) * 128 + nn);
                float4 v1 = *reinterpret_cast<const float4*>(
                    Wa + (size_t)(j * 128 + k0 + kr) * 128 + nn + 4);
                Bs[kr][nn + 0] = f2tf(v0.x); Bs[kr][nn + 1] = f2tf(v0.y);
                Bs[kr][nn + 2] = f2tf(v0.z); Bs[kr][nn + 3] = f2tf(v0.w);
                Bs[kr][nn + 4] = f2tf(v1.x); Bs[kr][nn + 5] = f2tf(v1.y);
                Bs[kr][nn + 6] = f2tf(v1.z); Bs[kr][nn + 7] = f2tf(v1.w);
            }
            __syncthreads();
#pragma unroll
            for (int kk = 0; kk < 32; kk += 8) {
                unsigned af[2][4];
#pragma unroll
                for (int mi = 0; mi < 2; mi++) {
                    int rb = warpM * 32 + mi * 16;
                    af[mi][0] = Cs[rb + ar][k0 + kk + ac];
                    af[mi][1] = Cs[rb + ar + 8][k0 + kk + ac];
                    af[mi][2] = Cs[rb + ar][k0 + kk + ac + 4];
                    af[mi][3] = Cs[rb + ar + 8][k0 + kk + ac + 4];
                }
#pragma unroll
                for (int ni = 0; ni < 8; ni++) {
                    int nb = warpN * 64 + ni * 8;
                    unsigned b0 = Bs[kk + bk][nb + bn];
                    unsigned b1 = Bs[kk + bk + 4][nb + bn];
#pragma unroll
                    for (int mi = 0; mi < 2; mi++)
                        MMA_TF32(accX[mi][ni], af[mi][0], af[mi][1], af[mi][2],
                                 af[mi][3], b0, b1);
                }
            }
        }
        __syncthreads();   // Cs/Bs reads done before next j overwrites
    }

    // final epilogue: ctx = accX + ba
#pragma unroll
    for (int mi = 0; mi < 2; mi++) {
        int rA = row0 + warpM * 32 + mi * 16 + (lane >> 2);
        int rB = rA + 8;
#pragma unroll
        for (int ni = 0; ni < 8; ni++) {
            int col = warpN * 64 + ni * 8 + (lane & 3) * 2;
            float b0 = ba[col], b1 = ba[col + 1];
            if (rA < M)
                *reinterpret_cast<float2*>(&ctx[rA * 128 + col]) =
                    make_float2(accX[mi][ni][0] + b0, accX[mi][ni][1] + b1);
            if (rB < M)
                *reinterpret_cast<float2*>(&ctx[rB * 128 + col]) =
                    make_float2(accX[mi][ni][2] + b0, accX[mi][ni][3] + b1);
        }
    }
}

// ---------------- fused GRU: gi-GEMM + gh-GEMM + gates + relu ----------------
__device__ __forceinline__ float sigm(float x) { return 1.f / (1.f + __expf(-x)); }

#define GRU_BSTRIDE 392   // mod 32 = 8: conflict-free B-fragment loads
#define GRU_SMEM ((2 * 64 * 36 + 2 * 32 * GRU_BSTRIDE) * 4)

__global__ __launch_bounds__(256)
void k_gru(const float* __restrict__ ctx, const float* __restrict__ h,
           const float* __restrict__ Wih, const float* __restrict__ Whh,
           const float* __restrict__ bih, const float* __restrict__ bhh,
           float* __restrict__ out, int M) {
    extern __shared__ unsigned sm_u[];
    unsigned (*Cs)[36] = (unsigned(*)[36])sm_u;                        // ctx 64x32
    unsigned (*Hs)[36] = (unsigned(*)[36])(sm_u + 64 * 36);            // h   64x32
    unsigned (*Bi)[GRU_BSTRIDE] = (unsigned(*)[GRU_BSTRIDE])(sm_u + 2 * 64 * 36);
    unsigned (*Bh)[GRU_BSTRIDE] =
        (unsigned(*)[GRU_BSTRIDE])(sm_u + 2 * 64 * 36 + 32 * GRU_BSTRIDE);

    const int t = threadIdx.x;
    const int lane = t & 31;
    const int warp = t >> 5;
    const int warpM = warp >> 1;
    const int warpN = warp & 1;
    const int row0 = blockIdx.x * 64;

    float accA[8][4], accB[8][4], accC[8][4], accD[8][4];
#pragma unroll
    for (int f = 0; f < 8; f++)
#pragma unroll
        for (int q = 0; q < 4; q++) {
            accA[f][q] = 0.f; accB[f][q] = 0.f;
            accC[f][q] = 0.f; accD[f][q] = 0.f;
        }

    const int ar = lane >> 2, ac = lane & 3;
    const int bk = lane & 3, bn = lane >> 2;

    for (int k0 = 0; k0 < 128; k0 += 32) {
#pragma unroll
        for (int i = 0; i < 2; i++) {
            int lin = t + i * 256;
            int r = lin >> 3;
            int kk = (lin & 7) << 2;
            int grow = row0 + r;
            float4 vc = {0, 0, 0, 0}, vh = {0, 0, 0, 0};
            if (grow < M) {
                vc = *reinterpret_cast<const float4*>(ctx + grow * 128 + k0 + kk);
                vh = *reinterpret_cast<const float4*>(h + grow * 128 + k0 + kk);
            }
            Cs[r][kk + 0] = f2tf(vc.x); Cs[r][kk + 1] = f2tf(vc.y);
            Cs[r][kk + 2] = f2tf(vc.z); Cs[r][kk + 3] = f2tf(vc.w);
            Hs[r][kk + 0] = f2tf(vh.x); Hs[r][kk + 1] = f2tf(vh.y);
            Hs[r][kk + 2] = f2tf(vh.z); Hs[r][kk + 3] = f2tf(vh.w);
        }
#pragma unroll
        for (int i = 0; i < 12; i++) {
            int lin = t + i * 256;
            int kr = lin / 96;
            int nn = (lin % 96) << 2;
            float4 vi = *reinterpret_cast<const float4*>(Wih + (k0 + kr) * 384 + nn);
            float4 vh = *reinterpret_cast<const float4*>(Whh + (k0 + kr) * 384 + nn);
            Bi[kr][nn + 0] = f2tf(vi.x); Bi[kr][nn + 1] = f2tf(vi.y);
            Bi[kr][nn + 2] = f2tf(vi.z); Bi[kr][nn + 3] = f2tf(vi.w);
            Bh[kr][nn + 0] = f2tf(vh.x); Bh[kr][nn + 1] = f2tf(vh.y);
            Bh[kr][nn + 2] = f2tf(vh.z); Bh[kr][nn + 3] = f2tf(vh.w);
        }
        __syncthreads();
#pragma unroll
        for (int kk = 0; kk < 32; kk += 8) {
            unsigned afc[4], afh[4];
            {
                int rb = warpM * 16;
                afc[0] = Cs[rb + ar][kk + ac];
                afc[1] = Cs[rb + ar + 8][kk + ac];
                afc[2] = Cs[rb + ar][kk + ac + 4];
                afc[3] = Cs[rb + ar + 8][kk + ac + 4];
                afh[0] = Hs[rb + ar][kk + ac];
                afh[1] = Hs[rb + ar + 8][kk + ac];
                afh[2] = Hs[rb + ar][kk + ac + 4];
                afh[3] = Hs[rb + ar + 8][kk + ac + 4];
            }
#pragma unroll
            for (int f = 0; f < 8; f++) {
                int nbr = 0 + warpN * 64 + f * 8;
                int nbz = 128 + warpN * 64 + f * 8;
                int nbn = 256 + warpN * 64 + f * 8;
                unsigned bir0 = Bi[kk + bk][nbr + bn], bir1 = Bi[kk + bk + 4][nbr + bn];
                unsigned bhr0 = Bh[kk + bk][nbr + bn], bhr1 = Bh[kk + bk + 4][nbr + bn];
                unsigned biz0 = Bi[kk + bk][nbz + bn], biz1 = Bi[kk + bk + 4][nbz + bn];
                unsigned bhz0 = Bh[kk + bk][nbz + bn], bhz1 = Bh[kk + bk + 4][nbz + bn];
                unsigned bin0 = Bi[kk + bk][nbn + bn], bin1 = Bi[kk + bk + 4][nbn + bn];
                unsigned bhn0 = Bh[kk + bk][nbn + bn], bhn1 = Bh[kk + bk + 4][nbn + bn];
                MMA_TF32(accA[f], afc[0], afc[1], afc[2], afc[3], bir0, bir1);
                MMA_TF32(accA[f], afh[0], afh[1], afh[2], afh[3], bhr0, bhr1);
                MMA_TF32(accB[f], afc[0], afc[1], afc[2], afc[3], biz0, biz1);
                MMA_TF32(accB[f], afh[0], afh[1], afh[2], afh[3], bhz0, bhz1);
                MMA_TF32(accC[f], afc[0], afc[1], afc[2], afc[3], bin0, bin1);
                MMA_TF32(accD[f], afh[0], afh[1], afh[2], afh[3], bhn0, bhn1);
            }
        }
        __syncthreads();
    }

    int rA = row0 + warpM * 16 + (lane >> 2);
    int rB = rA + 8;
#pragma unroll
    for (int f = 0; f < 8; f++) {
        int i0 = warpN * 64 + f * 8 + (lane & 3) * 2;
        float2 bi_r = *reinterpret_cast<const float2*>(&bih[i0]);
        float2 bi_z = *reinterpret_cast<const float2*>(&bih[128 + i0]);
        float2 bi_n = *reinterpret_cast<const float2*>(&bih[256 + i0]);
        float2 bh_r = *reinterpret_cast<const float2*>(&bhh[i0]);
        float2 bh_z = *reinterpret_cast<const float2*>(&bhh[128 + i0]);
        float2 bh_n = *reinterpret_cast<const float2*>(&bhh[256 + i0]);
#pragma unroll
        for (int half = 0; half < 2; half++) {
            int row = half ? rB : rA;
            int q = half * 2;
            if (row >= M) continue;
            float2 hv = *reinterpret_cast<const float2*>(&h[row * 128 + i0]);
            float r0 = sigm(accA[f][q]     + bi_r.x + bh_r.x);
            float r1 = sigm(accA[f][q + 1] + bi_r.y + bh_r.y);
            float z0 = sigm(accB[f][q]     + bi_z.x + bh_z.x);
            float z1 = sigm(accB[f][q + 1] + bi_z.y + bh_z.y);
            float n0 = tanhf(accC[f][q]     + bi_n.x + r0 * (accD[f][q]     + bh_n.x));
            float n1 = tanhf(accC[f][q + 1] + bi_n.y + r1 * (accD[f][q + 1] + bh_n.y));
            float o0 = fmaxf((1.f - z0) * n0 + z0 * hv.x, 0.f);
            float o1 = fmaxf((1.f - z1) * n1 + z1 * hv.y, 0.f);
            *reinterpret_cast<float2*>(&out[row * 128 + i0]) = make_float2(o0, o1);
        }
    }
}

// ---------------- launch ----------------
extern "C" void kernel_launch(void* const* d_in, const int* in_sizes, int n_in,
                              void* d_out, int out_size) {
    const int*   dst = (const int*)d_in[0];
    const float* l1  = (const float*)d_in[1];
    const float* l2  = (const float*)d_in[2];
    const float* l3  = (const float*)d_in[3];
    const float* ef1 = (const float*)d_in[4];
    const float* ef2 = (const float*)d_in[5];
    const float* ef3 = (const float*)d_in[6];
    const float* nf1 = (const float*)d_in[7];
    const float* nf2 = (const float*)d_in[8];
    const float* nf3 = (const float*)d_in[9];
    const float* W1  = (const float*)d_in[10];
    const float* b1  = (const float*)d_in[11];
    const float* W2  = (const float*)d_in[12];
    const float* b2  = (const float*)d_in[13];
    const float* W3  = (const float*)d_in[14];
    const float* b3  = (const float*)d_in[15];
    const float* Wa  = (const float*)d_in[16];
    const float* ba  = (const float*)d_in[17];
    const float* Wn  = (const float*)d_in[18];
    const float* bn  = (const float*)d_in[19];
    const float* Wih = (const float*)d_in[20];
    const float* bih = (const float*)d_in[21];
    const float* Whh = (const float*)d_in[22];
    const float* bhh = (const float*)d_in[23];

    const int E = in_sizes[0];
    const int N = in_sizes[7] / 128;

    float *p_agg, *p_ctx, *p_h, *p_s0, *p_s1, *p_s2;
    cudaGetSymbolAddress((void**)&p_agg, g_agg);
    cudaGetSymbolAddress((void**)&p_ctx, g_ctx);
    cudaGetSymbolAddress((void**)&p_h, g_h);
    cudaGetSymbolAddress((void**)&p_s0, g_ssum0);
    cudaGetSymbolAddress((void**)&p_s1, g_ssum1);
    cudaGetSymbolAddress((void**)&p_s2, g_ssum2);

    const int nch = (N + 1023) / 1024;
    const int mtiles = (N + 127) / 128;

    cudaFuncSetAttribute(gemm_tc<384, 0, true>,
                         cudaFuncAttributeMaxDynamicSharedMemorySize, GEMM_SMEM);
    cudaFuncSetAttribute(k_ctx,
                         cudaFuncAttributeMaxDynamicSharedMemorySize, CTX_SMEM);
    cudaFuncSetAttribute(k_gru,
                         cudaFuncAttributeMaxDynamicSharedMemorySize, GRU_SMEM);

    // exactly ONE side stream (two leaked pool memory past teardown in R7).
    // stream/events created per call, not destroyed: kernel_launch only
    // executes for correctness + capture.
    cudaStream_t s1;
    cudaStreamCreateWithFlags(&s1, cudaStreamNonBlocking);
    cudaEvent_t evF, evJ;
    cudaEventCreateWithFlags(&evF, cudaEventDisableTiming);
    cudaEventCreateWithFlags(&evJ, cudaEventDisableTiming);

    // fork s1: G2b = [nf1,nf2,nf3] @ Wn + bn (input-only dependency)
    cudaEventRecord(evF, 0);
    cudaStreamWaitEvent(s1, evF, 0);
    gemm_tc<384, 0, true><<<dim3(mtiles, 1, 1), 256, GEMM_SMEM, s1>>>(
        TriC{nf1, nf1, nf1}, nf2, nf3, 128, TriC{Wn, Wn, Wn}, 128,
        TriC{bn, bn, bn}, TriC{nullptr, nullptr, nullptr},
        TriO{p_h, p_h, p_h}, 128, N);
    cudaEventRecord(evJ, s1);

    // main stream: edge pipeline
    k_init<<<(N + 255) / 256, 256>>>(N);
    k_edge1<<<(E + 255) / 256, 256>>>(dst, l1, l2, l3, E);
    k_scan1<<<nch, 1024>>>(N);
    k_scan2<<<1, 64>>>(nch);
    k_scan3<<<nch, 1024>>>(N, E);
    k_edge2<<<(E + 255) / 256, 256>>>(dst, E);
    k_gather<<<(N + 7) / 8, 256>>>((const float4*)ef1, (const float4*)ef2,
                                   (const float4*)ef3, N);

    // fused G1+G2a: ctx = elu-blocks(agg) @ Wa + ba
    k_ctx<<<mtiles, 256, CTX_SMEM>>>(
        p_agg, TriC{W1, W2, W3}, TriC{b1, b2, b3}, TriC{p_s0, p_s1, p_s2},
        Wa, ba, p_ctx, N);

    // join G2b, then fused GRU (gi-GEMM + gh-GEMM + gates + relu)
    cudaStreamWaitEvent(0, evJ, 0);
    k_gru<<<(N + 63) / 64, 256, GRU_SMEM>>>(p_ctx, p_h, Wih, Whh, bih, bhh,
                                            (float*)d_out, N);
}

// round 11
// speedup vs baseline: 1.1278x; 1.1278x over previous
#include <cuda_runtime.h>
#include <cuda_bf16.h>
#include <math.h>

// Problem constants (fixed-shape problem)
#define NMAX 50048
#define EMAX 800000

// ---------------- device scratch (no allocations allowed) ----------------
__device__ int    g_cnt[NMAX];
__device__ int    g_rowptr[NMAX + 2];
__device__ int    g_wcur[NMAX];
__device__ int    g_eid[EMAX];
__device__ float  g_w0[EMAX];
__device__ float  g_w1[EMAX];
__device__ float  g_w2[EMAX];
__device__ float4 g_wp[EMAX];          // normalized (w0,w1,w2,0) in CSR order
__device__ float  g_ssum0[NMAX];       // after scan3: holds 1/sum (or 0)
__device__ float  g_ssum1[NMAX];
__device__ float  g_ssum2[NMAX];
__device__ float  g_agg[50000 * 384];
__device__ float  g_c[50000 * 384];
__device__ float  g_ctx[50000 * 128];
__device__ float  g_h[50000 * 128];
__device__ int    g_chunk[64];

// ---------------- small helpers ----------------
__device__ __forceinline__ unsigned f2tf(float x) {
    unsigned r;
    asm("cvt.rna.tf32.f32 %0, %1;" : "=r"(r) : "f"(x));
    return r;
}
__device__ __forceinline__ unsigned s2u(const void* p) {
    unsigned r;
    asm("{ .reg .u64 t; cvta.to.shared.u64 t, %1; cvt.u32.u64 %0, t; }"
        : "=r"(r) : "l"(p));
    return r;
}
#define CP16(dst, src, sz) \
    asm volatile("cp.async.cg.shared.global [%0], [%1], 16, %2;" \
                 :: "r"(dst), "l"(src), "r"(sz))
#define CPCOMMIT() asm volatile("cp.async.commit_group;")
#define CPWAIT(n)  asm volatile("cp.async.wait_group %0;" :: "n"(n))
#define MMA_TF32(acc, a0, a1, a2, a3, b0, b1) \
    asm volatile( \
        "mma.sync.aligned.m16n8k8.row.col.f32.tf32.tf32.f32 " \
        "{%0,%1,%2,%3}, {%4,%5,%6,%7}, {%8,%9}, {%0,%1,%2,%3};" \
        : "+f"((acc)[0]), "+f"((acc)[1]), "+f"((acc)[2]), "+f"((acc)[3]) \
        : "r"(a0), "r"(a1), "r"(a2), "r"(a3), "r"(b0), "r"(b1))

// ---------------- init ----------------
__global__ void k_init(int N) {
    int i = blockIdx.x * blockDim.x + threadIdx.x;
    if (i < N) {
        g_cnt[i] = 0;
        g_ssum0[i] = 0.f; g_ssum1[i] = 0.f; g_ssum2[i] = 0.f;
    }
}

// ---------------- edge pass 1: histogram + exp + exp-sums ----------------
__global__ void k_edge1(const int* __restrict__ dst,
                        const float* __restrict__ l1,
                        const float* __restrict__ l2,
                        const float* __restrict__ l3, int E) {
    int e = blockIdx.x * blockDim.x + threadIdx.x;
    if (e >= E) return;
    int d = dst[e];
    atomicAdd(&g_cnt[d], 1);
    float w0 = __expf(l1[e]);
    float w1 = __expf(l2[e]);
    float w2 = __expf(l3[e]);
    g_w0[e] = w0; g_w1[e] = w1; g_w2[e] = w2;
    atomicAdd(&g_ssum0[d], w0);
    atomicAdd(&g_ssum1[d], w1);
    atomicAdd(&g_ssum2[d], w2);
}

// ---------------- scan (two kernels; chunk offsets folded into scan3) --------
__global__ void k_scan1(int N) {
    __shared__ int sh[1024];
    int t = threadIdx.x;
    int n = blockIdx.x * 1024 + t;
    int v = (n < N) ? g_cnt[n] : 0;
    sh[t] = v;
    __syncthreads();
#pragma unroll
    for (int off = 1; off < 1024; off <<= 1) {
        int x = (t >= off) ? sh[t - off] : 0;
        __syncthreads();
        sh[t] += x;
        __syncthreads();
    }
    if (n < N) g_rowptr[n] = sh[t] - v;
    if (t == 1023) g_chunk[blockIdx.x] = sh[1023];
}

__global__ void k_scan3(int N, int E) {
    // each block computes its own chunk offset (<=49 adds, trivial)
    __shared__ int off_sh;
    if (threadIdx.x == 0) {
        int run = 0;
        for (int i = 0; i < (int)blockIdx.x; i++) run += g_chunk[i];
        off_sh = run;
    }
    __syncthreads();
    int n = blockIdx.x * 1024 + threadIdx.x;
    if (n < N) {
        int v = g_rowptr[n] + off_sh;
        g_rowptr[n] = v;
        g_wcur[n] = v;
        float s0 = g_ssum0[n]; g_ssum0[n] = (s0 > 0.f) ? 1.f / s0 : 0.f;
        float s1 = g_ssum1[n]; g_ssum1[n] = (s1 > 0.f) ? 1.f / s1 : 0.f;
        float s2 = g_ssum2[n]; g_ssum2[n] = (s2 > 0.f) ? 1.f / s2 : 0.f;
    }
    if (n == 0) g_rowptr[N] = E;
}

// ---------------- edge pass 2: scatter edge ids + normalized packed weights ----
__global__ void k_edge2(const int* __restrict__ dst, int E) {
    int e = blockIdx.x * blockDim.x + threadIdx.x;
    if (e >= E) return;
    int d = dst[e];
    int p = atomicAdd(&g_wcur[d], 1);
    g_eid[p] = e;
    float4 w;
    w.x = g_w0[e] * g_ssum0[d];
    w.y = g_w1[e] * g_ssum1[d];
    w.z = g_w2[e] * g_ssum2[d];
    w.w = 0.f;
    g_wp[p] = w;
}

// ---------------- gather: agg_i[n] = sum_e a_i(e) * ef_i[e] ----------------
__global__ void k_gather(const float4* __restrict__ ef1,
                         const float4* __restrict__ ef2,
                         const float4* __restrict__ ef3, int N) {
    int warp = blockIdx.x * 8 + (threadIdx.x >> 5);
    int lane = threadIdx.x & 31;
    if (warp >= N) return;
    int s = g_rowptr[warp];
    int eend = g_rowptr[warp + 1];
    float4 a0 = {0, 0, 0, 0}, a1 = {0, 0, 0, 0}, a2 = {0, 0, 0, 0};
    int k = s;
    for (; k + 4 <= eend; k += 4) {
        int e0 = g_eid[k], e1 = g_eid[k + 1], e2 = g_eid[k + 2], e3 = g_eid[k + 3];
        float4 wA = g_wp[k], wB = g_wp[k + 1], wC = g_wp[k + 2], wD = g_wp[k + 3];
        float4 u0 = ef1[e0 * 32 + lane], u1 = ef1[e1 * 32 + lane];
        float4 u2 = ef1[e2 * 32 + lane], u3 = ef1[e3 * 32 + lane];
        float4 v0 = ef2[e0 * 32 + lane], v1 = ef2[e1 * 32 + lane];
        float4 v2 = ef2[e2 * 32 + lane], v3 = ef2[e3 * 32 + lane];
        float4 x0 = ef3[e0 * 32 + lane], x1 = ef3[e1 * 32 + lane];
        float4 x2 = ef3[e2 * 32 + lane], x3 = ef3[e3 * 32 + lane];
        a0.x += wA.x * u0.x + wB.x * u1.x + wC.x * u2.x + wD.x * u3.x;
        a0.y += wA.x * u0.y + wB.x * u1.y + wC.x * u2.y + wD.x * u3.y;
        a0.z += wA.x * u0.z + wB.x * u1.z + wC.x * u2.z + wD.x * u3.z;
        a0.w += wA.x * u0.w + wB.x * u1.w + wC.x * u2.w + wD.x * u3.w;
        a1.x += wA.y * v0.x + wB.y * v1.x + wC.y * v2.x + wD.y * v3.x;
        a1.y += wA.y * v0.y + wB.y * v1.y + wC.y * v2.y + wD.y * v3.y;
        a1.z += wA.y * v0.z + wB.y * v1.z + wC.y * v2.z + wD.y * v3.z;
        a1.w += wA.y * v0.w + wB.y * v1.w + wC.y * v2.w + wD.y * v3.w;
        a2.x += wA.z * x0.x + wB.z * x1.x + wC.z * x2.x + wD.z * x3.x;
        a2.y += wA.z * x0.y + wB.z * x1.y + wC.z * x2.y + wD.z * x3.y;
        a2.z += wA.z * x0.z + wB.z * x1.z + wC.z * x2.z + wD.z * x3.z;
        a2.w += wA.z * x0.w + wB.z * x1.w + wC.z * x2.w + wD.z * x3.w;
    }
    for (; k < eend; k++) {
        int e = g_eid[k];
        float4 w = g_wp[k];
        float4 u = ef1[e * 32 + lane];
        float4 v = ef2[e * 32 + lane];
        float4 x = ef3[e * 32 + lane];
        a0.x += w.x * u.x; a0.y += w.x * u.y; a0.z += w.x * u.z; a0.w += w.x * u.w;
        a1.x += w.y * v.x; a1.y += w.y * v.y; a1.z += w.y * v.z; a1.w += w.y * v.w;
        a2.x += w.z * x.x; a2.y += w.z * x.y; a2.z += w.z * x.z; a2.w += w.z * x.w;
    }
    float4* out = reinterpret_cast<float4*>(g_agg) + warp * 96;
    out[lane]      = a0;
    out[32 + lane] = a1;
    out[64 + lane] = a2;
}

// ---------------- TF32 tensor-core GEMM (cp.async 3-stage pipelined) ----------------
struct TriC { const float* p0; const float* p1; const float* p2; };
struct TriO { float* p0; float* p1; float* p2; };
__device__ __forceinline__ const float* sel(const TriC& t, int z) {
    return z == 0 ? t.p0 : (z == 1 ? t.p1 : t.p2);
}
__device__ __forceinline__ float* sel(const TriO& t, int z) {
    return z == 0 ? t.p0 : (z == 1 ? t.p1 : t.p2);
}

#define GEMM_ASZ (128 * 36)
#define GEMM_BSZ (32 * 136)
#define GEMM_STAGE (GEMM_ASZ + GEMM_BSZ)
#define GEMM_SMEM (3 * GEMM_STAGE * 4)

template <int KTOT, int EPI, bool CONCAT3>
__global__ __launch_bounds__(256, 2)
void gemm_tc(TriC a0t, const float* __restrict__ A1, const float* __restrict__ A2,
             int lda, TriC bt, int ldb, TriC biast, TriC flagt,
             TriO ct, int ldc, int M) {
    extern __shared__ float smem[];
    const int z = blockIdx.z;
    const float* __restrict__ A0 = sel(a0t, z);
    const float* __restrict__ B = sel(bt, z);
    const float* __restrict__ bias = sel(biast, z);
    const float* __restrict__ flag_s = sel(flagt, z);
    float* __restrict__ C = sel(ct, z);

    const int t = threadIdx.x;
    const int lane = t & 31;
    const int warp = t >> 5;
    const int warpM = warp >> 1;
    const int warpN = warp & 1;
    const int row0 = blockIdx.x * 128;
    const int coff = blockIdx.y * 128;

    float acc[2][8][4];
#pragma unroll
    for (int i = 0; i < 2; i++)
#pragma unroll
        for (int j = 0; j < 8; j++)
#pragma unroll
            for (int q = 0; q < 4; q++) acc[i][j][q] = 0.f;

    const int ar = lane >> 2, ac = lane & 3;
    const int bk = lane & 3, bn = lane >> 2;
    const int NKB = KTOT / 32;

    auto issue_tile = [&](int kb) {
        float* stage = smem + (kb % 3) * GEMM_STAGE;
        float* As = stage;
        float* Bs = stage + GEMM_ASZ;
        int k0 = kb * 32;
#pragma unroll
        for (int i = 0; i < 4; i++) {
            int lin = t + i * 256;
            int r = lin >> 3;
            int kk = (lin & 7) << 2;
            int grow = row0 + r;
            bool ok = grow < M;
            const float* src;
            int kg = k0 + kk;
            if (CONCAT3) {
                const float* Ap = (kg < 128) ? A0 : ((kg < 256) ? A1 : A2);
                src = ok ? (Ap + grow * 128 + (kg & 127)) : A0;
            } else {
                src = ok ? (A0 + grow * lda + kg) : A0;
            }
            CP16(s2u(As + r * 36 + kk), src, ok ? 16 : 0);
        }
#pragma unroll
        for (int i = 0; i < 4; i++) {
            int lin = t + i * 256;
            int kr = lin >> 5;
            int nn = (lin & 31) << 2;
            CP16(s2u(Bs + kr * 136 + nn), B + (k0 + kr) * ldb + coff + nn, 16);
        }
    };

    issue_tile(0); CPCOMMIT();
    if (NKB > 1) { issue_tile(1); CPCOMMIT(); }

    for (int kb = 0; kb < NKB; kb++) {
        if (kb + 1 < NKB) { CPWAIT(1); } else { CPWAIT(0); }
        __syncthreads();
        if (kb + 2 < NKB) { issue_tile(kb + 2); CPCOMMIT(); }

        float* stage = smem + (kb % 3) * GEMM_STAGE;
        float* As = stage;
        float* Bs = stage + GEMM_ASZ;
#pragma unroll
        for (int kk = 0; kk < 32; kk += 8) {
            unsigned af[2][4];
#pragma unroll
            for (int mi = 0; mi < 2; mi++) {
                int rb = warpM * 32 + mi * 16;
                af[mi][0] = f2tf(As[(rb + ar) * 36 + kk + ac]);
                af[mi][1] = f2tf(As[(rb + ar + 8) * 36 + kk + ac]);
                af[mi][2] = f2tf(As[(rb + ar) * 36 + kk + ac + 4]);
                af[mi][3] = f2tf(As[(rb + ar + 8) * 36 + kk + ac + 4]);
            }
            unsigned bf[8][2];
#pragma unroll
            for (int ni = 0; ni < 8; ni++) {
                int nb = warpN * 64 + ni * 8;
                bf[ni][0] = f2tf(Bs[(kk + bk) * 136 + nb + bn]);
                bf[ni][1] = f2tf(Bs[(kk + bk + 4) * 136 + nb + bn]);
            }
#pragma unroll
            for (int mi = 0; mi < 2; mi++)
#pragma unroll
                for (int ni = 0; ni < 8; ni++)
                    MMA_TF32(acc[mi][ni], af[mi][0], af[mi][1], af[mi][2],
                             af[mi][3], bf[ni][0], bf[ni][1]);
        }
    }

#pragma unroll
    for (int mi = 0; mi < 2; mi++) {
        int rA = row0 + warpM * 32 + mi * 16 + (lane >> 2);
        int rB = rA + 8;
        float flA = 1.f, flB = 1.f;
        if (EPI == 1) {
            flA = (rA < M && flag_s[rA] > 0.f) ? 1.f : 0.f;
            flB = (rB < M && flag_s[rB] > 0.f) ? 1.f : 0.f;
        }
#pragma unroll
        for (int ni = 0; ni < 8; ni++) {
            int col = coff + warpN * 64 + ni * 8 + (lane & 3) * 2;
            float b0 = bias[col], b1 = bias[col + 1];
            if (rA < M) {
                float v0, v1;
                if (EPI == 1) {
                    v0 = acc[mi][ni][0] + b0 * flA;
                    v1 = acc[mi][ni][1] + b1 * flA;
                    v0 = (v0 > 0.f) ? v0 : expm1f(v0);
                    v1 = (v1 > 0.f) ? v1 : expm1f(v1);
                } else {
                    v0 = acc[mi][ni][0] + b0;
                    v1 = acc[mi][ni][1] + b1;
                }
                *reinterpret_cast<float2*>(&C[rA * ldc + col]) = make_float2(v0, v1);
            }
            if (rB < M) {
                float v2, v3;
                if (EPI == 1) {
                    v2 = acc[mi][ni][2] + b0 * flB;
                    v3 = acc[mi][ni][3] + b1 * flB;
                    v2 = (v2 > 0.f) ? v2 : expm1f(v2);
                    v3 = (v3 > 0.f) ? v3 : expm1f(v3);
                } else {
                    v2 = acc[mi][ni][2] + b0;
                    v3 = acc[mi][ni][3] + b1;
                }
                *reinterpret_cast<float2*>(&C[rB * ldc + col]) = make_float2(v2, v3);
            }
        }
    }
}

// ---------------- fused GRU: gi-GEMM + gh-GEMM + gates + relu ----------------
__device__ __forceinline__ float sigm(float x) { return 1.f / (1.f + __expf(-x)); }

#define GRU_BSTRIDE 392
#define GRU_SMEM ((2 * 64 * 36 + 2 * 32 * GRU_BSTRIDE) * 4)

__global__ __launch_bounds__(256)
void k_gru(const float* __restrict__ ctx, const float* __restrict__ h,
           const float* __restrict__ Wih, const float* __restrict__ Whh,
           const float* __restrict__ bih, const float* __restrict__ bhh,
           float* __restrict__ out, int M) {
    extern __shared__ unsigned sm_u[];
    unsigned (*Cs)[36] = (unsigned(*)[36])sm_u;
    unsigned (*Hs)[36] = (unsigned(*)[36])(sm_u + 64 * 36);
    unsigned (*Bi)[GRU_BSTRIDE] = (unsigned(*)[GRU_BSTRIDE])(sm_u + 2 * 64 * 36);
    unsigned (*Bh)[GRU_BSTRIDE] =
        (unsigned(*)[GRU_BSTRIDE])(sm_u + 2 * 64 * 36 + 32 * GRU_BSTRIDE);

    const int t = threadIdx.x;
    const int lane = t & 31;
    const int warp = t >> 5;
    const int warpM = warp >> 1;
    const int warpN = warp & 1;
    const int row0 = blockIdx.x * 64;

    float accA[8][4], accB[8][4], accC[8][4], accD[8][4];
#pragma unroll
    for (int f = 0; f < 8; f++)
#pragma unroll
        for (int q = 0; q < 4; q++) {
            accA[f][q] = 0.f; accB[f][q] = 0.f;
            accC[f][q] = 0.f; accD[f][q] = 0.f;
        }

    const int ar = lane >> 2, ac = lane & 3;
    const int bk = lane & 3, bn = lane >> 2;

    for (int k0 = 0; k0 < 128; k0 += 32) {
#pragma unroll
        for (int i = 0; i < 2; i++) {
            int lin = t + i * 256;
            int r = lin >> 3;
            int kk = (lin & 7) << 2;
            int grow = row0 + r;
            float4 vc = {0, 0, 0, 0}, vh = {0, 0, 0, 0};
            if (grow < M) {
                vc = *reinterpret_cast<const float4*>(ctx + grow * 128 + k0 + kk);
                vh = *reinterpret_cast<const float4*>(h + grow * 128 + k0 + kk);
            }
            Cs[r][kk + 0] = f2tf(vc.x); Cs[r][kk + 1] = f2tf(vc.y);
            Cs[r][kk + 2] = f2tf(vc.z); Cs[r][kk + 3] = f2tf(vc.w);
            Hs[r][kk + 0] = f2tf(vh.x); Hs[r][kk + 1] = f2tf(vh.y);
            Hs[r][kk + 2] = f2tf(vh.z); Hs[r][kk + 3] = f2tf(vh.w);
        }
#pragma unroll
        for (int i = 0; i < 12; i++) {
            int lin = t + i * 256;
            int kr = lin / 96;
            int nn = (lin % 96) << 2;
            float4 vi = *reinterpret_cast<const float4*>(Wih + (k0 + kr) * 384 + nn);
            float4 vh = *reinterpret_cast<const float4*>(Whh + (k0 + kr) * 384 + nn);
            Bi[kr][nn + 0] = f2tf(vi.x); Bi[kr][nn + 1] = f2tf(vi.y);
            Bi[kr][nn + 2] = f2tf(vi.z); Bi[kr][nn + 3] = f2tf(vi.w);
            Bh[kr][nn + 0] = f2tf(vh.x); Bh[kr][nn + 1] = f2tf(vh.y);
            Bh[kr][nn + 2] = f2tf(vh.z); Bh[kr][nn + 3] = f2tf(vh.w);
        }
        __syncthreads();
#pragma unroll
        for (int kk = 0; kk < 32; kk += 8) {
            unsigned afc[4], afh[4];
            {
                int rb = warpM * 16;
                afc[0] = Cs[rb + ar][kk + ac];
                afc[1] = Cs[rb + ar + 8][kk + ac];
                afc[2] = Cs[rb + ar][kk + ac + 4];
                afc[3] = Cs[rb + ar + 8][kk + ac + 4];
                afh[0] = Hs[rb + ar][kk + ac];
                afh[1] = Hs[rb + ar + 8][kk + ac];
                afh[2] = Hs[rb + ar][kk + ac + 4];
                afh[3] = Hs[rb + ar + 8][kk + ac + 4];
            }
#pragma unroll
            for (int f = 0; f < 8; f++) {
                int nbr = 0 + warpN * 64 + f * 8;
                int nbz = 128 + warpN * 64 + f * 8;
                int nbn = 256 + warpN * 64 + f * 8;
                unsigned bir0 = Bi[kk + bk][nbr + bn], bir1 = Bi[kk + bk + 4][nbr + bn];
                unsigned bhr0 = Bh[kk + bk][nbr + bn], bhr1 = Bh[kk + bk + 4][nbr + bn];
                unsigned biz0 = Bi[kk + bk][nbz + bn], biz1 = Bi[kk + bk + 4][nbz + bn];
                unsigned bhz0 = Bh[kk + bk][nbz + bn], bhz1 = Bh[kk + bk + 4][nbz + bn];
                unsigned bin0 = Bi[kk + bk][nbn + bn], bin1 = Bi[kk + bk + 4][nbn + bn];
                unsigned bhn0 = Bh[kk + bk][nbn + bn], bhn1 = Bh[kk + bk + 4][nbn + bn];
                MMA_TF32(accA[f], afc[0], afc[1], afc[2], afc[3], bir0, bir1);
                MMA_TF32(accA[f], afh[0], afh[1], afh[2], afh[3], bhr0, bhr1);
                MMA_TF32(accB[f], afc[0], afc[1], afc[2], afc[3], biz0, biz1);
                MMA_TF32(accB[f], afh[0], afh[1], afh[2], afh[3], bhz0, bhz1);
                MMA_TF32(accC[f], afc[0], afc[1], afc[2], afc[3], bin0, bin1);
                MMA_TF32(accD[f], afh[0], afh[1], afh[2], afh[3], bhn0, bhn1);
            }
        }
        __syncthreads();
    }

    int rA = row0 + warpM * 16 + (lane >> 2);
    int rB = rA + 8;
#pragma unroll
    for (int f = 0; f < 8; f++) {
        int i0 = warpN * 64 + f * 8 + (lane & 3) * 2;
        float2 bi_r = *reinterpret_cast<const float2*>(&bih[i0]);
        float2 bi_z = *reinterpret_cast<const float2*>(&bih[128 + i0]);
        float2 bi_n = *reinterpret_cast<const float2*>(&bih[256 + i0]);
        float2 bh_r = *reinterpret_cast<const float2*>(&bhh[i0]);
        float2 bh_z = *reinterpret_cast<const float2*>(&bhh[128 + i0]);
        float2 bh_n = *reinterpret_cast<const float2*>(&bhh[256 + i0]);
#pragma unroll
        for (int half = 0; half < 2; half++) {
            int row = half ? rB : rA;
            int q = half * 2;
            if (row >= M) continue;
            float2 hv = *reinterpret_cast<const float2*>(&h[row * 128 + i0]);
            float r0 = sigm(accA[f][q]     + bi_r.x + bh_r.x);
            float r1 = sigm(accA[f][q + 1] + bi_r.y + bh_r.y);
            float z0 = sigm(accB[f][q]     + bi_z.x + bh_z.x);
            float z1 = sigm(accB[f][q + 1] + bi_z.y + bh_z.y);
            float n0 = tanhf(accC[f][q]     + bi_n.x + r0 * (accD[f][q]     + bh_n.x));
            float n1 = tanhf(accC[f][q + 1] + bi_n.y + r1 * (accD[f][q + 1] + bh_n.y));
            float o0 = fmaxf((1.f - z0) * n0 + z0 * hv.x, 0.f);
            float o1 = fmaxf((1.f - z1) * n1 + z1 * hv.y, 0.f);
            *reinterpret_cast<float2*>(&out[row * 128 + i0]) = make_float2(o0, o1);
        }
    }
}

// ---------------- launch ----------------
extern "C" void kernel_launch(void* const* d_in, const int* in_sizes, int n_in,
                              void* d_out, int out_size) {
    const int*   dst = (const int*)d_in[0];
    const float* l1  = (const float*)d_in[1];
    const float* l2  = (const float*)d_in[2];
    const float* l3  = (const float*)d_in[3];
    const float* ef1 = (const float*)d_in[4];
    const float* ef2 = (const float*)d_in[5];
    const float* ef3 = (const float*)d_in[6];
    const float* nf1 = (const float*)d_in[7];
    const float* nf2 = (const float*)d_in[8];
    const float* nf3 = (const float*)d_in[9];
    const float* W1  = (const float*)d_in[10];
    const float* b1  = (const float*)d_in[11];
    const float* W2  = (const float*)d_in[12];
    const float* b2  = (const float*)d_in[13];
    const float* W3  = (const float*)d_in[14];
    const float* b3  = (const float*)d_in[15];
    const float* Wa  = (const float*)d_in[16];
    const float* ba  = (const float*)d_in[17];
    const float* Wn  = (const float*)d_in[18];
    const float* bn  = (const float*)d_in[19];
    const float* Wih = (const float*)d_in[20];
    const float* bih = (const float*)d_in[21];
    const float* Whh = (const float*)d_in[22];
    const float* bhh = (const float*)d_in[23];

    const int E = in_sizes[0];
    const int N = in_sizes[7] / 128;

    float *p_agg, *p_c, *p_ctx, *p_h, *p_s0, *p_s1, *p_s2;
    cudaGetSymbolAddress((void**)&p_agg, g_agg);
    cudaGetSymbolAddress((void**)&p_c, g_c);
    cudaGetSymbolAddress((void**)&p_ctx, g_ctx);
    cudaGetSymbolAddress((void**)&p_h, g_h);
    cudaGetSymbolAddress((void**)&p_s0, g_ssum0);
    cudaGetSymbolAddress((void**)&p_s1, g_ssum1);
    cudaGetSymbolAddress((void**)&p_s2, g_ssum2);

    const int nch = (N + 1023) / 1024;
    const int mtiles = (N + 127) / 128;

    cudaFuncSetAttribute(gemm_tc<384, 0, true>,
                         cudaFuncAttributeMaxDynamicSharedMemorySize, GEMM_SMEM);
    cudaFuncSetAttribute(gemm_tc<128, 1, false>,
                         cudaFuncAttributeMaxDynamicSharedMemorySize, GEMM_SMEM);
    cudaFuncSetAttribute(gemm_tc<384, 0, false>,
                         cudaFuncAttributeMaxDynamicSharedMemorySize, GEMM_SMEM);
    cudaFuncSetAttribute(k_gru,
                         cudaFuncAttributeMaxDynamicSharedMemorySize, GRU_SMEM);

    // exactly ONE side stream (two leaked pool memory past teardown in R7).
    // stream/events created per call, not destroyed: kernel_launch only
    // executes for correctness + capture.
    cudaStream_t s1;
    cudaStreamCreateWithFlags(&s1, cudaStreamNonBlocking);
    cudaEvent_t evF, evJ;
    cudaEventCreateWithFlags(&evF, cudaEventDisableTiming);
    cudaEventCreateWithFlags(&evJ, cudaEventDisableTiming);

    // fork s1: G2b = [nf1,nf2,nf3] @ Wn + bn (input-only dependency)
    cudaEventRecord(evF, 0);
    cudaStreamWaitEvent(s1, evF, 0);
    gemm_tc<384, 0, true><<<dim3(mtiles, 1, 1), 256, GEMM_SMEM, s1>>>(
        TriC{nf1, nf1, nf1}, nf2, nf3, 128, TriC{Wn, Wn, Wn}, 128,
        TriC{bn, bn, bn}, TriC{nullptr, nullptr, nullptr},
        TriO{p_h, p_h, p_h}, 128, N);
    cudaEventRecord(evJ, s1);

    // main stream: edge pipeline
    k_init<<<(N + 255) / 256, 256>>>(N);
    k_edge1<<<(E + 255) / 256, 256>>>(dst, l1, l2, l3, E);
    k_scan1<<<nch, 1024>>>(N);
    k_scan3<<<nch, 1024>>>(N, E);
    k_edge2<<<(E + 255) / 256, 256>>>(dst, E);
    k_gather<<<(N + 7) / 8, 256>>>((const float4*)ef1, (const float4*)ef2,
                                   (const float4*)ef3, N);

    // G1 batched: c_j = elu(agg_j @ W_j + b_j * flag_j), j=0..2 via grid.z
    gemm_tc<128, 1, false><<<dim3(mtiles, 1, 3), 256, GEMM_SMEM>>>(
        TriC{p_agg, p_agg + 128, p_agg + 256}, nullptr, nullptr, 384,
        TriC{W1, W2, W3}, 128, TriC{b1, b2, b3}, TriC{p_s0, p_s1, p_s2},
        TriO{p_c, p_c + 128, p_c + 256}, 384, N);

    // G2a: ctx = c @ Wa + ba
    gemm_tc<384, 0, false><<<dim3(mtiles, 1, 1), 256, GEMM_SMEM>>>(
        TriC{p_c, nullptr, nullptr}, nullptr, nullptr, 384,
        TriC{Wa, nullptr, nullptr}, 128, TriC{ba, nullptr, nullptr},
        TriC{nullptr, nullptr, nullptr}, TriO{p_ctx, nullptr, nullptr}, 128, N);

    // join G2b, then fused GRU (gi-GEMM + gh-GEMM + gates + relu)
    cudaStreamWaitEvent(0, evJ, 0);
    k_gru<<<(N + 63) / 64, 256, GRU_SMEM>>>(p_ctx, p_h, Wih, Whh, bih, bhh,
                                            (float*)d_out, N);
}